// round 14
// baseline (speedup 1.0000x reference)
#include <cuda_runtime.h>
#include <cuda_fp16.h>
#include <math.h>
#include <stdint.h>

static constexpr int SEQ   = 2048;
static constexpr int DM    = 2048;
static constexpr int NHEAD = 16;
static constexpr int HDIM  = 128;
static constexpr int NROWS = 4096;   // B * L

// ---------------- scratch (device globals; no allocation allowed) ----------
__device__ __align__(16) __half g_h  [(size_t)NROWS * DM];          // rms out (half)
__device__ __align__(16) __half g_qkv[(size_t)NROWS * 3 * DM];      // qkv (half)
__device__ __align__(16) __half g_q  [(size_t)NROWS * DM];          // rope'd half
__device__ __align__(16) __half g_k  [(size_t)NROWS * DM];
__device__ __align__(16) __half g_v  [(size_t)NROWS * DM];
__device__ __align__(16) __half g_o  [(size_t)NROWS * DM];          // attn out (half)
__device__ __align__(16) float  g_x1 [(size_t)NROWS * DM];          // residual fp32
__device__ __align__(16) __half g_ff [(size_t)NROWS * 4 * DM];      // swiglu out (half)
// half TRANSPOSED weights: Wqkv^T | Wo^T | Wp^T(permuted) | Wff^T
__device__ __align__(16) __half g_w  [(size_t)67108864];

__device__ __forceinline__ void cp_async16(uint32_t smem, const void* g) {
    asm volatile("cp.async.cg.shared.global [%0], [%1], 16;" :: "r"(smem), "l"(g));
}
__device__ __forceinline__ void cp_commit() {
    asm volatile("cp.async.commit_group;");
}
template<int N> __device__ __forceinline__ void cp_wait() {
    asm volatile("cp.async.wait_group %0;" :: "n"(N));
}

#define MMA_F16(acc, a0, a1, a2, a3, b0, b1)                                   \
    asm volatile(                                                              \
        "mma.sync.aligned.m16n8k16.row.col.f32.f16.f16.f32 "                   \
        "{%0,%1,%2,%3}, {%4,%5,%6,%7}, {%8,%9}, {%0,%1,%2,%3};"                \
        : "+f"(acc[0]), "+f"(acc[1]), "+f"(acc[2]), "+f"(acc[3])               \
        : "r"(a0), "r"(a1), "r"(a2), "r"(a3), "r"(b0), "r"(b1))

// ---------------- weight half convert + transpose: Wt[n][k] = W[k][n] --------
// 64(k) x 32(n) tiles: 128B-coalesced loads AND stores, conflict-free smem.
// PERM: swiglu row permutation for Wp (gate/value interleaved per 64-row block)
template<bool PERM>
__global__ __launch_bounds__(256)
void cvtw_t_kernel(const float* __restrict__ W, __half* __restrict__ Wt,
                   int K, int N)
{
    __shared__ float tile[32][65];    // [n][k]
    int tid = threadIdx.x;
    int n0 = blockIdx.x * 32, k0 = blockIdx.y * 64;
    #pragma unroll
    for (int it = 0; it < 8; it++) {
        int idx = it * 256 + tid;
        int r = idx >> 5, c = idx & 31;
        tile[c][r] = W[(size_t)(k0 + r) * N + n0 + c];
    }
    __syncthreads();
    int wid = tid >> 5, lane = tid & 31;
    #pragma unroll
    for (int j = 0; j < 4; j++) {
        int nrow = wid + 8 * j;
        int n = n0 + nrow;
        int r = n;
        if (PERM) {
            int half_n = N >> 1;                 // 8192
            if (n < half_n) r = (n >> 5) * 64 + (n & 31);
            else { int f = n - half_n; r = (f >> 5) * 64 + 32 + (f & 31); }
        }
        float v0 = tile[nrow][2 * lane];
        float v1 = tile[nrow][2 * lane + 1];
        *(__half2*)(Wt + (size_t)r * K + k0 + 2 * lane) = __floats2half2_rn(v0, v1);
    }
}

// ---------------- RMSNorm (half output) --------------------------------------
__global__ __launch_bounds__(256)
void rmsnorm_kernel(const float* __restrict__ x, const float* __restrict__ g,
                    __half* __restrict__ out)
{
    int row = blockIdx.x;
    int tid = threadIdx.x;
    const float4* xr = (const float4*)(x + (size_t)row * DM);
    const float4* gr = (const float4*)g;
    float4 v0 = xr[2*tid], v1 = xr[2*tid + 1];
    float ss = v0.x*v0.x + v0.y*v0.y + v0.z*v0.z + v0.w*v0.w
             + v1.x*v1.x + v1.y*v1.y + v1.z*v1.z + v1.w*v1.w;
    #pragma unroll
    for (int off = 16; off > 0; off >>= 1)
        ss += __shfl_xor_sync(0xffffffffu, ss, off);
    __shared__ float wsum[8];
    if ((tid & 31) == 0) wsum[tid >> 5] = ss;
    __syncthreads();
    float tot = wsum[0]+wsum[1]+wsum[2]+wsum[3]+wsum[4]+wsum[5]+wsum[6]+wsum[7];
    float sc = rsqrtf(tot * (1.0f / (float)DM) + 1e-8f);
    float4 ga = gr[2*tid], gb = gr[2*tid + 1];
    __half2 h0 = __floats2half2_rn(v0.x*sc*ga.x, v0.y*sc*ga.y);
    __half2 h1 = __floats2half2_rn(v0.z*sc*ga.z, v0.w*sc*ga.w);
    __half2 h2 = __floats2half2_rn(v1.x*sc*gb.x, v1.y*sc*gb.y);
    __half2 h3 = __floats2half2_rn(v1.z*sc*gb.z, v1.w*sc*gb.w);
    uint4 pk;
    pk.x = *(uint32_t*)&h0; pk.y = *(uint32_t*)&h1;
    pk.z = *(uint32_t*)&h2; pk.w = *(uint32_t*)&h3;
    ((uint4*)(out + (size_t)row * DM))[tid] = pk;
}

// ---------------- FP16 tensor-core GEMM, cp.async 3-stage pipeline -----------
// MODE 0: float out + optional residual; MODE 1: half out; MODE 2: swiglu->half
// 256x128 CTA tile, BK=64, 3-stage (issue-after-barrier, race-free),
// 8 warps (4x2), warp tile 64x64. Smem: 3 x (256+128) x 72 halves = 165,888 B.
template<int MODE>
__global__ __launch_bounds__(256, 1)
void hgemm_kernel(const __half* __restrict__ A, const __half* __restrict__ Bt,
                  const float* __restrict__ bias, const float* __restrict__ res,
                  void* __restrict__ Cv, int M, int N, int K)
{
    extern __shared__ __half hsm[];
    __half* As = hsm;                  // 3 stages x 256 x 72
    __half* Bs = hsm + 55296;          // 3 stages x 128 x 72

    int tid = threadIdx.x;
    int wid = tid >> 5, lane = tid & 31;
    int wm  = wid >> 1;        // 0..3 -> 64 rows
    int wn  = wid & 1;         // 0..1 -> 64 cols
    int g   = lane >> 2;       // 0..7
    int tig = lane & 3;        // 0..3

    const __half* Ab = A  + (size_t)blockIdx.y * 256 * K;
    const __half* Bb = Bt + (size_t)blockIdx.x * 128 * K;

    uint32_t as_base = (uint32_t)__cvta_generic_to_shared(As);
    uint32_t bs_base = (uint32_t)__cvta_generic_to_shared(Bs);

    int arow[8], acol8[8], brow[4], bcol8[4];
    #pragma unroll
    for (int i = 0; i < 8; i++) {
        int c = tid + 256 * i;
        arow[i] = c >> 3; acol8[i] = (c & 7) * 8;
    }
    #pragma unroll
    for (int i = 0; i < 4; i++) {
        int c = tid + 256 * i;
        brow[i] = c >> 3; bcol8[i] = (c & 7) * 8;
    }

    float acc[4][8][4];
    #pragma unroll
    for (int i = 0; i < 4; i++)
        #pragma unroll
        for (int j = 0; j < 8; j++) {
            acc[i][j][0] = 0.f; acc[i][j][1] = 0.f;
            acc[i][j][2] = 0.f; acc[i][j][3] = 0.f;
        }

    const int NT = K >> 6;

    // prologue: fill stages 0 and 1
    #pragma unroll
    for (int s = 0; s < 2; s++) {
        int k0 = s * 64;
        uint32_t aoff = as_base + (uint32_t)(s * 18432 * 2);
        uint32_t boff = bs_base + (uint32_t)(s * 9216 * 2);
        #pragma unroll
        for (int i = 0; i < 8; i++)
            cp_async16(aoff + (uint32_t)((arow[i] * 72 + acol8[i]) * 2),
                       Ab + (size_t)arow[i] * K + k0 + acol8[i]);
        #pragma unroll
        for (int i = 0; i < 4; i++)
            cp_async16(boff + (uint32_t)((brow[i] * 72 + bcol8[i]) * 2),
                       Bb + (size_t)brow[i] * K + k0 + bcol8[i]);
        cp_commit();
    }

    for (int t = 0; t < NT; t++) {
        if (t + 1 < NT) cp_wait<1>(); else cp_wait<0>();
        __syncthreads();   // stage (t+2)%3 fully consumed (at iter t-1) by all warps

        if (t + 2 < NT) {
            int s = (t + 2) % 3;
            int k0 = (t + 2) * 64;
            uint32_t aoff = as_base + (uint32_t)(s * 18432 * 2);
            uint32_t boff = bs_base + (uint32_t)(s * 9216 * 2);
            #pragma unroll
            for (int i = 0; i < 8; i++)
                cp_async16(aoff + (uint32_t)((arow[i] * 72 + acol8[i]) * 2),
                           Ab + (size_t)arow[i] * K + k0 + acol8[i]);
            #pragma unroll
            for (int i = 0; i < 4; i++)
                cp_async16(boff + (uint32_t)((brow[i] * 72 + bcol8[i]) * 2),
                           Bb + (size_t)brow[i] * K + k0 + bcol8[i]);
            cp_commit();
        }

        int abuf = (t % 3) * 18432, bbuf = (t % 3) * 9216;
        #pragma unroll
        for (int ks = 0; ks < 4; ks++) {
            int kb = ks * 16;
            uint32_t af[4][4], bf[8][2];
            #pragma unroll
            for (int mi = 0; mi < 4; mi++) {
                int row = wm * 64 + mi * 16 + g;
                const __half* r0 = &As[abuf + row * 72 + kb + 2 * tig];
                const __half* r1 = &As[abuf + (row + 8) * 72 + kb + 2 * tig];
                af[mi][0] = *(const uint32_t*)r0;
                af[mi][1] = *(const uint32_t*)r1;
                af[mi][2] = *(const uint32_t*)(r0 + 8);
                af[mi][3] = *(const uint32_t*)(r1 + 8);
            }
            #pragma unroll
            for (int ni = 0; ni < 8; ni++) {
                int col = wn * 64 + ni * 8 + g;
                const __half* b0 = &Bs[bbuf + col * 72 + kb + 2 * tig];
                bf[ni][0] = *(const uint32_t*)b0;
                bf[ni][1] = *(const uint32_t*)(b0 + 8);
            }
            #pragma unroll
            for (int mi = 0; mi < 4; mi++)
                #pragma unroll
                for (int ni = 0; ni < 8; ni++)
                    MMA_F16(acc[mi][ni], af[mi][0], af[mi][1], af[mi][2], af[mi][3],
                            bf[ni][0], bf[ni][1]);
        }
    }

    if (MODE == 2) {
        // swiglu fused: warp block holds [gate f..f+31 | value f..f+31]
        __half* FF = (__half*)Cv;
        int b = blockIdx.x * 2 + wn;
        #pragma unroll
        for (int mi = 0; mi < 4; mi++) {
            int row = blockIdx.y * 256 + wm * 64 + mi * 16 + g;
            #pragma unroll
            for (int ni = 0; ni < 4; ni++) {
                int off = ni * 8 + 2 * tig;
                int f   = b * 32 + off;              // ff column
                float bg0 = bias[f],        bg1 = bias[f + 1];
                float bv0 = bias[8192 + f], bv1 = bias[8192 + f + 1];
                #pragma unroll
                for (int rr = 0; rr < 2; rr++) {
                    float gt0 = acc[mi][ni][2*rr]   + bg0;
                    float gt1 = acc[mi][ni][2*rr+1] + bg1;
                    float vl0 = acc[mi][ni+4][2*rr]   + bv0;
                    float vl1 = acc[mi][ni+4][2*rr+1] + bv1;
                    float r0 = gt0 / (1.0f + expf(-gt0)) * vl0;
                    float r1 = gt1 / (1.0f + expf(-gt1)) * vl1;
                    __half2 h = __floats2half2_rn(r0, r1);
                    *(__half2*)(FF + (size_t)(row + 8*rr) * (4*DM) + f) = h;
                }
            }
        }
    } else {
        #pragma unroll
        for (int mi = 0; mi < 4; mi++) {
            #pragma unroll
            for (int ni = 0; ni < 8; ni++) {
                int row = blockIdx.y * 256 + wm * 64 + mi * 16 + g;
                int col = blockIdx.x * 128 + wn * 64 + ni * 8 + 2 * tig;
                float bx = bias[col], by = bias[col + 1];
                size_t off0 = (size_t)row * N + col;
                size_t off1 = (size_t)(row + 8) * N + col;
                float r0x = acc[mi][ni][0] + bx, r0y = acc[mi][ni][1] + by;
                float r1x = acc[mi][ni][2] + bx, r1y = acc[mi][ni][3] + by;
                if (MODE == 1) {
                    __half* C = (__half*)Cv;
                    *(__half2*)(C + off0) = __floats2half2_rn(r0x, r0y);
                    *(__half2*)(C + off1) = __floats2half2_rn(r1x, r1y);
                } else {
                    float* C = (float*)Cv;
                    if (res) {
                        float2 q0 = *(const float2*)(res + off0);
                        float2 q1 = *(const float2*)(res + off1);
                        r0x += q0.x; r0y += q0.y;
                        r1x += q1.x; r1y += q1.y;
                    }
                    *(float2*)(C + off0) = make_float2(r0x, r0y);
                    *(float2*)(C + off1) = make_float2(r1x, r1y);
                }
            }
        }
    }
}

// ---------------- RoPE + head split: qkv(half) -> Q/K/V half -----------------
__global__ __launch_bounds__(256)
void rope_split_kernel(const __half* __restrict__ qkv)
{
    int idx = blockIdx.x * 256 + threadIdx.x;
    int i   = idx & 63;
    int h   = (idx >> 6) & 15;
    int row = idx >> 10;          // b*SEQ + l
    int l   = row & (SEQ - 1);
    int b   = row >> 11;
    const __half* base = qkv + (size_t)row * (3 * DM) + h * HDIM;
    float q0 = __half2float(base[i]),        q1 = __half2float(base[i + 64]);
    float k0 = __half2float(base[DM + i]),   k1 = __half2float(base[DM + i + 64]);
    float invf = powf(10000.0f, -(float)(2 * i) * (1.0f / 128.0f));
    float ang = (float)l * invf;
    float sn, cs;
    sincosf(ang, &sn, &cs);
    size_t ob = ((size_t)((b * NHEAD + h) * SEQ + l)) * HDIM;
    g_q[ob + i]      = __float2half(q0 * cs - q1 * sn);
    g_q[ob + i + 64] = __float2half(q1 * cs + q0 * sn);
    g_k[ob + i]      = __float2half(k0 * cs - k1 * sn);
    g_k[ob + i + 64] = __float2half(k1 * cs + k0 * sn);
    g_v[ob + i]      = base[2*DM + i];
    g_v[ob + i + 64] = base[2*DM + i + 64];
}

// ---------------- FP16 MMA causal flash attention (no ldmatrix) --------------
// 4 warps, 64 queries/CTA, key tiles of 64. V transposed into smem at load time
// (Vt[d][key], stride 72, key-XOR swizzle) so PV B-frags are plain LDS.32.
// Smem (half): Qs[64][136] + Ks[64][136] + Vt[128][72] + Ps[64][72] = 62,464 B.
// LPT: blockIdx.x = head, blockIdx.y = reversed q-tile.
__global__ __launch_bounds__(128)
void attn_kernel(const __half* __restrict__ Q, const __half* __restrict__ K,
                 const __half* __restrict__ V, __half* __restrict__ O)
{
    extern __shared__ __half hsm_[];
    __half* Qs = hsm_;               // 64*136
    __half* Ks = Qs + 64 * 136;
    __half* Vt = Ks + 64 * 136;      // 128*72 (transposed, swizzled)
    __half* Ps = Vt + 128 * 72;      // 64*72

    int tid = threadIdx.x;
    int wid = tid >> 5, lane = tid & 31;
    int g = lane >> 2, tig = lane & 3;
    int bh = blockIdx.x;
    int q0 = (gridDim.y - 1 - blockIdx.y) * 64;    // longest CTAs first
    const __half* Qb = Q + (size_t)bh * SEQ * HDIM;
    const __half* Kb = K + (size_t)bh * SEQ * HDIM;
    const __half* Vb = V + (size_t)bh * SEQ * HDIM;

    #pragma unroll
    for (int it = 0; it < 8; it++) {
        int idx = it * 128 + tid;
        int r = idx >> 4, c8 = idx & 15;
        *(uint4*)&Qs[r * 136 + c8 * 8] =
            *(const uint4*)(Qb + (size_t)(q0 + r) * HDIM + c8 * 8);
    }

    const float scale = 0.08838834764831845f;   // 1/sqrt(128)
    float mrow[2] = {-INFINITY, -INFINITY};
    float lrow[2] = {0.f, 0.f};
    float oacc[16][4];
    #pragma unroll
    for (int d = 0; d < 16; d++) {
        oacc[d][0] = 0.f; oacc[d][1] = 0.f; oacc[d][2] = 0.f; oacc[d][3] = 0.f;
    }

    int arow0 = (wid * 16 + g) * 136;
    int arow1 = (wid * 16 + g + 8) * 136;
    int prow0 = (wid * 16 + g) * 72;
    int prow1 = (wid * 16 + g + 8) * 72;
    int qrow0 = q0 + wid * 16 + g;
    int qrow1 = qrow0 + 8;

    for (int n0 = 0; n0 <= q0; n0 += 64) {
        __syncthreads();
        #pragma unroll
        for (int it = 0; it < 8; it++) {
            int idx = it * 128 + tid;
            int r = idx >> 4, c8 = idx & 15;
            *(uint4*)&Ks[r * 136 + c8 * 8] =
                *(const uint4*)(Kb + (size_t)(n0 + r) * HDIM + c8 * 8);
            uint4 vv4 = *(const uint4*)(Vb + (size_t)(n0 + r) * HDIM + c8 * 8);
            const __half* vv = (const __half*)&vv4;
            int kcol = r ^ ((c8 & 7) * 8);
            #pragma unroll
            for (int j = 0; j < 8; j++)
                Vt[(c8 * 8 + j) * 72 + kcol] = vv[j];
        }
        __syncthreads();

        float sacc[8][4];
        #pragma unroll
        for (int ni = 0; ni < 8; ni++) {
            sacc[ni][0] = 0.f; sacc[ni][1] = 0.f;
            sacc[ni][2] = 0.f; sacc[ni][3] = 0.f;
        }
        #pragma unroll
        for (int kc = 0; kc < 8; kc++) {
            int kb = kc * 16;
            uint32_t a0 = *(const uint32_t*)&Qs[arow0 + kb + 2*tig];
            uint32_t a1 = *(const uint32_t*)&Qs[arow1 + kb + 2*tig];
            uint32_t a2 = *(const uint32_t*)&Qs[arow0 + kb + 8 + 2*tig];
            uint32_t a3 = *(const uint32_t*)&Qs[arow1 + kb + 8 + 2*tig];
            #pragma unroll
            for (int ni = 0; ni < 8; ni++) {
                const __half* bp = &Ks[(ni*8 + g) * 136 + kb + 2*tig];
                uint32_t b0 = *(const uint32_t*)bp;
                uint32_t b1 = *(const uint32_t*)(bp + 8);
                MMA_F16(sacc[ni], a0, a1, a2, a3, b0, b1);
            }
        }

        bool diag = (n0 == q0);
        float tm0 = -INFINITY, tm1 = -INFINITY;
        #pragma unroll
        for (int ni = 0; ni < 8; ni++) {
            int n = n0 + ni * 8 + 2 * tig;
            float s0 = sacc[ni][0] * scale;
            float s1 = sacc[ni][1] * scale;
            float s2 = sacc[ni][2] * scale;
            float s3 = sacc[ni][3] * scale;
            if (diag) {
                if (n     > qrow0) s0 = -INFINITY;
                if (n + 1 > qrow0) s1 = -INFINITY;
                if (n     > qrow1) s2 = -INFINITY;
                if (n + 1 > qrow1) s3 = -INFINITY;
            }
            sacc[ni][0] = s0; sacc[ni][1] = s1;
            sacc[ni][2] = s2; sacc[ni][3] = s3;
            tm0 = fmaxf(tm0, fmaxf(s0, s1));
            tm1 = fmaxf(tm1, fmaxf(s2, s3));
        }
        tm0 = fmaxf(tm0, __shfl_xor_sync(0xffffffffu, tm0, 1));
        tm0 = fmaxf(tm0, __shfl_xor_sync(0xffffffffu, tm0, 2));
        tm1 = fmaxf(tm1, __shfl_xor_sync(0xffffffffu, tm1, 1));
        tm1 = fmaxf(tm1, __shfl_xor_sync(0xffffffffu, tm1, 2));

        float mn0 = fmaxf(mrow[0], tm0), mn1 = fmaxf(mrow[1], tm1);
        float corr0 = expf(mrow[0] - mn0), corr1 = expf(mrow[1] - mn1);
        float ps0 = 0.f, ps1 = 0.f;
        #pragma unroll
        for (int ni = 0; ni < 8; ni++) {
            float p0 = expf(sacc[ni][0] - mn0);
            float p1 = expf(sacc[ni][1] - mn0);
            float p2 = expf(sacc[ni][2] - mn1);
            float p3 = expf(sacc[ni][3] - mn1);
            ps0 += p0 + p1; ps1 += p2 + p3;
            *(__half2*)&Ps[prow0 + ni*8 + 2*tig] = __floats2half2_rn(p0, p1);
            *(__half2*)&Ps[prow1 + ni*8 + 2*tig] = __floats2half2_rn(p2, p3);
        }
        ps0 += __shfl_xor_sync(0xffffffffu, ps0, 1);
        ps0 += __shfl_xor_sync(0xffffffffu, ps0, 2);
        ps1 += __shfl_xor_sync(0xffffffffu, ps1, 1);
        ps1 += __shfl_xor_sync(0xffffffffu, ps1, 2);
        lrow[0] = lrow[0] * corr0 + ps0;
        lrow[1] = lrow[1] * corr1 + ps1;
        mrow[0] = mn0; mrow[1] = mn1;
        #pragma unroll
        for (int d = 0; d < 16; d++) {
            oacc[d][0] *= corr0; oacc[d][1] *= corr0;
            oacc[d][2] *= corr1; oacc[d][3] *= corr1;
        }
        __syncwarp();

        #pragma unroll
        for (int kc = 0; kc < 4; kc++) {
            int kb = kc * 16;
            uint32_t a0 = *(const uint32_t*)&Ps[prow0 + kb + 2*tig];
            uint32_t a1 = *(const uint32_t*)&Ps[prow1 + kb + 2*tig];
            uint32_t a2 = *(const uint32_t*)&Ps[prow0 + kb + 8 + 2*tig];
            uint32_t a3 = *(const uint32_t*)&Ps[prow1 + kb + 8 + 2*tig];
            #pragma unroll
            for (int dt = 0; dt < 16; dt++) {
                int swz = (dt & 7) * 8;
                const __half* vrow = &Vt[(dt * 8 + g) * 72];
                uint32_t b0 = *(const uint32_t*)&vrow[(kb + 2*tig)     ^ swz];
                uint32_t b1 = *(const uint32_t*)&vrow[(kb + 2*tig + 8) ^ swz];
                MMA_F16(oacc[dt], a0, a1, a2, a3, b0, b1);
            }
        }
        __syncwarp();
    }

    float inv0 = 1.0f / lrow[0], inv1 = 1.0f / lrow[1];
    int b = bh >> 4, h = bh & 15;
    __half* d0 = O + ((size_t)(b * SEQ + qrow0)) * DM + h * HDIM;
    __half* d1 = O + ((size_t)(b * SEQ + qrow1)) * DM + h * HDIM;
    #pragma unroll
    for (int dt = 0; dt < 16; dt++) {
        int col = dt * 8 + 2 * tig;
        *(__half2*)(d0 + col) = __floats2half2_rn(oacc[dt][0]*inv0, oacc[dt][1]*inv0);
        *(__half2*)(d1 + col) = __floats2half2_rn(oacc[dt][2]*inv1, oacc[dt][3]*inv1);
    }
}

// ---------------- launch -----------------------------------------------------
extern "C" void kernel_launch(void* const* d_in, const int* in_sizes, int n_in,
                              void* d_out, int out_size)
{
    const float* x    = (const float*)d_in[0];
    const float* Wqkv = (const float*)d_in[1];
    const float* bqkv = (const float*)d_in[2];
    const float* Wo   = (const float*)d_in[3];
    const float* bo   = (const float*)d_in[4];
    const float* g1   = (const float*)d_in[5];
    const float* g2   = (const float*)d_in[6];
    const float* Wp   = (const float*)d_in[7];
    const float* bp   = (const float*)d_in[8];
    const float* Wff  = (const float*)d_in[9];
    const float* bff  = (const float*)d_in[10];
    float* out = (float*)d_out;

    __half *pH, *pQKV, *pQ, *pK, *pV, *pO, *pFF, *pW;
    float *pX1;
    cudaGetSymbolAddress((void**)&pH,   g_h);
    cudaGetSymbolAddress((void**)&pQKV, g_qkv);
    cudaGetSymbolAddress((void**)&pQ,   g_q);
    cudaGetSymbolAddress((void**)&pK,   g_k);
    cudaGetSymbolAddress((void**)&pV,   g_v);
    cudaGetSymbolAddress((void**)&pO,   g_o);
    cudaGetSymbolAddress((void**)&pX1,  g_x1);
    cudaGetSymbolAddress((void**)&pFF,  g_ff);
    cudaGetSymbolAddress((void**)&pW,   g_w);

    __half* wqkv = pW;                       // [6144 x 2048]
    __half* wo   = pW + 12582912;            // [2048 x 2048]
    __half* wp   = pW + 16777216;            // [16384 x 2048] (permuted rows)
    __half* wff  = pW + 50331648;            // [2048 x 8192]

    static constexpr int GEMM_SMEM = 165888;
    static constexpr int ATTN_SMEM = 62464;
    cudaFuncSetAttribute(hgemm_kernel<0>, cudaFuncAttributeMaxDynamicSharedMemorySize, GEMM_SMEM);
    cudaFuncSetAttribute(hgemm_kernel<1>, cudaFuncAttributeMaxDynamicSharedMemorySize, GEMM_SMEM);
    cudaFuncSetAttribute(hgemm_kernel<2>, cudaFuncAttributeMaxDynamicSharedMemorySize, GEMM_SMEM);
    cudaFuncSetAttribute(attn_kernel, cudaFuncAttributeMaxDynamicSharedMemorySize, ATTN_SMEM);

    // 0. convert + transpose weights to half (Wp with swiglu row permutation)
    cvtw_t_kernel<false><<<dim3(6144/32,  2048/64), 256>>>(Wqkv, wqkv, 2048, 6144);
    cvtw_t_kernel<false><<<dim3(2048/32,  2048/64), 256>>>(Wo,   wo,   2048, 2048);
    cvtw_t_kernel<true ><<<dim3(16384/32, 2048/64), 256>>>(Wp,   wp,   2048, 16384);
    cvtw_t_kernel<false><<<dim3(2048/32,  8192/64), 256>>>(Wff,  wff,  8192, 2048);

    // 1. h = rms(x, g1)  (half)
    rmsnorm_kernel<<<NROWS, 256>>>(x, g1, pH);
    // 2. qkv = h @ Wqkv + bqkv  (half out)
    hgemm_kernel<1><<<dim3(6144/128, NROWS/256), 256, GEMM_SMEM>>>(
        pH, wqkv, bqkv, nullptr, pQKV, NROWS, 3*DM, DM);
    // 3. rope + split into Q/K/V (half)
    rope_split_kernel<<<(NROWS * NHEAD * 64) / 256, 256>>>(pQKV);
    // 4. causal attention -> O (half, fp16 MMA, LPT order)
    attn_kernel<<<dim3(2*NHEAD, SEQ/64), 128, ATTN_SMEM>>>(pQ, pK, pV, pO);
    // 5. x1 = O @ Wo + bo + x  (fp32 out, residual)
    hgemm_kernel<0><<<dim3(DM/128, NROWS/256), 256, GEMM_SMEM>>>(
        pO, wo, bo, x, pX1, NROWS, DM, DM);
    // 6. h2 = rms(x1, g2)  (half)
    rmsnorm_kernel<<<NROWS, 256>>>(pX1, g2, pH);
    // 7+8. ff = swiglu(h2 @ Wp + bp)  fused  (half out)
    hgemm_kernel<2><<<dim3(16384/128, NROWS/256), 256, GEMM_SMEM>>>(
        pH, wp, bp, nullptr, pFF, NROWS, 8*DM, DM);
    // 9. out = ff @ Wff_out + bff + x1  (fp32 out, residual)
    hgemm_kernel<0><<<dim3(DM/128, NROWS/256), 256, GEMM_SMEM>>>(
        pFF, wff, bff, pX1, out, NROWS, DM, 4*DM);
}

// round 15
// speedup vs baseline: 1.5431x; 1.5431x over previous
#include <cuda_runtime.h>
#include <cuda_fp16.h>
#include <math.h>
#include <stdint.h>

static constexpr int SEQ   = 2048;
static constexpr int DM    = 2048;
static constexpr int NHEAD = 16;
static constexpr int HDIM  = 128;
static constexpr int NROWS = 4096;   // B * L

// ---------------- scratch (device globals; no allocation allowed) ----------
__device__ __align__(16) __half g_h  [(size_t)NROWS * DM];          // rms out (half)
__device__ __align__(16) __half g_qkv[(size_t)NROWS * 3 * DM];      // qkv (half)
__device__ __align__(16) __half g_q  [(size_t)NROWS * DM];          // rope'd half
__device__ __align__(16) __half g_k  [(size_t)NROWS * DM];
__device__ __align__(16) __half g_v  [(size_t)NROWS * DM];
__device__ __align__(16) __half g_o  [(size_t)NROWS * DM];          // attn out (half)
__device__ __align__(16) float  g_x1 [(size_t)NROWS * DM];          // residual fp32
__device__ __align__(16) __half g_ff [(size_t)NROWS * 4 * DM];      // swiglu out (half)
// half TRANSPOSED weights: Wqkv^T | Wo^T | Wp^T(permuted) | Wff^T
__device__ __align__(16) __half g_w  [(size_t)67108864];

__device__ __forceinline__ void cp_async16(uint32_t smem, const void* g) {
    asm volatile("cp.async.cg.shared.global [%0], [%1], 16;" :: "r"(smem), "l"(g));
}
__device__ __forceinline__ void cp_commit() {
    asm volatile("cp.async.commit_group;");
}
template<int N> __device__ __forceinline__ void cp_wait() {
    asm volatile("cp.async.wait_group %0;" :: "n"(N));
}

#define MMA_F16(acc, a0, a1, a2, a3, b0, b1)                                   \
    asm volatile(                                                              \
        "mma.sync.aligned.m16n8k16.row.col.f32.f16.f16.f32 "                   \
        "{%0,%1,%2,%3}, {%4,%5,%6,%7}, {%8,%9}, {%0,%1,%2,%3};"                \
        : "+f"(acc[0]), "+f"(acc[1]), "+f"(acc[2]), "+f"(acc[3])               \
        : "r"(a0), "r"(a1), "r"(a2), "r"(a3), "r"(b0), "r"(b1))

// ---------------- weight half convert + transpose: Wt[n][k] = W[k][n] --------
// 64(k) x 32(n) tiles: 128B-coalesced loads AND stores, conflict-free smem.
// PERM: swiglu row permutation for Wp (gate/value interleaved per 64-row block)
template<bool PERM>
__global__ __launch_bounds__(256)
void cvtw_t_kernel(const float* __restrict__ W, __half* __restrict__ Wt,
                   int K, int N)
{
    __shared__ float tile[32][65];    // [n][k]
    int tid = threadIdx.x;
    int n0 = blockIdx.x * 32, k0 = blockIdx.y * 64;
    #pragma unroll
    for (int it = 0; it < 8; it++) {
        int idx = it * 256 + tid;
        int r = idx >> 5, c = idx & 31;
        tile[c][r] = W[(size_t)(k0 + r) * N + n0 + c];
    }
    __syncthreads();
    int wid = tid >> 5, lane = tid & 31;
    #pragma unroll
    for (int j = 0; j < 4; j++) {
        int nrow = wid + 8 * j;
        int n = n0 + nrow;
        int r = n;
        if (PERM) {
            int half_n = N >> 1;                 // 8192
            if (n < half_n) r = (n >> 5) * 64 + (n & 31);
            else { int f = n - half_n; r = (f >> 5) * 64 + 32 + (f & 31); }
        }
        float v0 = tile[nrow][2 * lane];
        float v1 = tile[nrow][2 * lane + 1];
        *(__half2*)(Wt + (size_t)r * K + k0 + 2 * lane) = __floats2half2_rn(v0, v1);
    }
}

// ---------------- RMSNorm (half output) --------------------------------------
__global__ __launch_bounds__(256)
void rmsnorm_kernel(const float* __restrict__ x, const float* __restrict__ g,
                    __half* __restrict__ out)
{
    int row = blockIdx.x;
    int tid = threadIdx.x;
    const float4* xr = (const float4*)(x + (size_t)row * DM);
    const float4* gr = (const float4*)g;
    float4 v0 = xr[2*tid], v1 = xr[2*tid + 1];
    float ss = v0.x*v0.x + v0.y*v0.y + v0.z*v0.z + v0.w*v0.w
             + v1.x*v1.x + v1.y*v1.y + v1.z*v1.z + v1.w*v1.w;
    #pragma unroll
    for (int off = 16; off > 0; off >>= 1)
        ss += __shfl_xor_sync(0xffffffffu, ss, off);
    __shared__ float wsum[8];
    if ((tid & 31) == 0) wsum[tid >> 5] = ss;
    __syncthreads();
    float tot = wsum[0]+wsum[1]+wsum[2]+wsum[3]+wsum[4]+wsum[5]+wsum[6]+wsum[7];
    float sc = rsqrtf(tot * (1.0f / (float)DM) + 1e-8f);
    float4 ga = gr[2*tid], gb = gr[2*tid + 1];
    __half2 h0 = __floats2half2_rn(v0.x*sc*ga.x, v0.y*sc*ga.y);
    __half2 h1 = __floats2half2_rn(v0.z*sc*ga.z, v0.w*sc*ga.w);
    __half2 h2 = __floats2half2_rn(v1.x*sc*gb.x, v1.y*sc*gb.y);
    __half2 h3 = __floats2half2_rn(v1.z*sc*gb.z, v1.w*sc*gb.w);
    uint4 pk;
    pk.x = *(uint32_t*)&h0; pk.y = *(uint32_t*)&h1;
    pk.z = *(uint32_t*)&h2; pk.w = *(uint32_t*)&h3;
    ((uint4*)(out + (size_t)row * DM))[tid] = pk;
}

// ---------------- FP16 tensor-core GEMM, cp.async double-buffered ------------
// R13-proven 2-stage version (3-stage regressed; reverted).
// MODE 0: float out + optional residual; MODE 1: half out; MODE 2: swiglu->half
// 256x128 CTA tile, BK=64, 2-stage, 8 warps (4x2), warp tile 64x64.
template<int MODE>
__global__ __launch_bounds__(256, 1)
void hgemm_kernel(const __half* __restrict__ A, const __half* __restrict__ Bt,
                  const float* __restrict__ bias, const float* __restrict__ res,
                  void* __restrict__ Cv, int M, int N, int K)
{
    extern __shared__ __half hsm[];
    __half* As = hsm;                  // 2 stages x 256 x 72
    __half* Bs = hsm + 36864;          // 2 stages x 128 x 72

    int tid = threadIdx.x;
    int wid = tid >> 5, lane = tid & 31;
    int wm  = wid >> 1;        // 0..3 -> 64 rows
    int wn  = wid & 1;         // 0..1 -> 64 cols
    int g   = lane >> 2;       // 0..7
    int tig = lane & 3;        // 0..3

    const __half* Ab = A  + (size_t)blockIdx.y * 256 * K;
    const __half* Bb = Bt + (size_t)blockIdx.x * 128 * K;

    uint32_t as_base = (uint32_t)__cvta_generic_to_shared(As);
    uint32_t bs_base = (uint32_t)__cvta_generic_to_shared(Bs);

    int arow[8], acol8[8], brow[4], bcol8[4];
    #pragma unroll
    for (int i = 0; i < 8; i++) {
        int c = tid + 256 * i;
        arow[i] = c >> 3; acol8[i] = (c & 7) * 8;
    }
    #pragma unroll
    for (int i = 0; i < 4; i++) {
        int c = tid + 256 * i;
        brow[i] = c >> 3; bcol8[i] = (c & 7) * 8;
    }

    float acc[4][8][4];
    #pragma unroll
    for (int i = 0; i < 4; i++)
        #pragma unroll
        for (int j = 0; j < 8; j++) {
            acc[i][j][0] = 0.f; acc[i][j][1] = 0.f;
            acc[i][j][2] = 0.f; acc[i][j][3] = 0.f;
        }

    const int NT = K >> 6;

    #pragma unroll
    for (int i = 0; i < 8; i++)
        cp_async16(as_base + (uint32_t)((arow[i] * 72 + acol8[i]) * 2),
                   Ab + (size_t)arow[i] * K + acol8[i]);
    #pragma unroll
    for (int i = 0; i < 4; i++)
        cp_async16(bs_base + (uint32_t)((brow[i] * 72 + bcol8[i]) * 2),
                   Bb + (size_t)brow[i] * K + bcol8[i]);
    cp_commit();

    for (int t = 0; t < NT; t++) {
        int buf = t & 1;
        if (t + 1 < NT) {
            int nb = (t + 1) & 1;
            int k0 = (t + 1) * 64;
            uint32_t aoff = as_base + (uint32_t)(nb * 18432 * 2);
            uint32_t boff = bs_base + (uint32_t)(nb * 9216 * 2);
            #pragma unroll
            for (int i = 0; i < 8; i++)
                cp_async16(aoff + (uint32_t)((arow[i] * 72 + acol8[i]) * 2),
                           Ab + (size_t)arow[i] * K + k0 + acol8[i]);
            #pragma unroll
            for (int i = 0; i < 4; i++)
                cp_async16(boff + (uint32_t)((brow[i] * 72 + bcol8[i]) * 2),
                           Bb + (size_t)brow[i] * K + k0 + bcol8[i]);
            cp_commit();
            cp_wait<1>();
        } else {
            cp_wait<0>();
        }
        __syncthreads();

        int abuf = buf * 18432, bbuf = buf * 9216;
        #pragma unroll
        for (int ks = 0; ks < 4; ks++) {
            int kb = ks * 16;
            uint32_t af[4][4], bf[8][2];
            #pragma unroll
            for (int mi = 0; mi < 4; mi++) {
                int row = wm * 64 + mi * 16 + g;
                const __half* r0 = &As[abuf + row * 72 + kb + 2 * tig];
                const __half* r1 = &As[abuf + (row + 8) * 72 + kb + 2 * tig];
                af[mi][0] = *(const uint32_t*)r0;
                af[mi][1] = *(const uint32_t*)r1;
                af[mi][2] = *(const uint32_t*)(r0 + 8);
                af[mi][3] = *(const uint32_t*)(r1 + 8);
            }
            #pragma unroll
            for (int ni = 0; ni < 8; ni++) {
                int col = wn * 64 + ni * 8 + g;
                const __half* b0 = &Bs[bbuf + col * 72 + kb + 2 * tig];
                bf[ni][0] = *(const uint32_t*)b0;
                bf[ni][1] = *(const uint32_t*)(b0 + 8);
            }
            #pragma unroll
            for (int mi = 0; mi < 4; mi++)
                #pragma unroll
                for (int ni = 0; ni < 8; ni++)
                    MMA_F16(acc[mi][ni], af[mi][0], af[mi][1], af[mi][2], af[mi][3],
                            bf[ni][0], bf[ni][1]);
        }
        __syncthreads();
    }

    if (MODE == 2) {
        // swiglu fused: warp block holds [gate f..f+31 | value f..f+31]
        __half* FF = (__half*)Cv;
        int b = blockIdx.x * 2 + wn;
        #pragma unroll
        for (int mi = 0; mi < 4; mi++) {
            int row = blockIdx.y * 256 + wm * 64 + mi * 16 + g;
            #pragma unroll
            for (int ni = 0; ni < 4; ni++) {
                int off = ni * 8 + 2 * tig;
                int f   = b * 32 + off;              // ff column
                float bg0 = bias[f],        bg1 = bias[f + 1];
                float bv0 = bias[8192 + f], bv1 = bias[8192 + f + 1];
                #pragma unroll
                for (int rr = 0; rr < 2; rr++) {
                    float gt0 = acc[mi][ni][2*rr]   + bg0;
                    float gt1 = acc[mi][ni][2*rr+1] + bg1;
                    float vl0 = acc[mi][ni+4][2*rr]   + bv0;
                    float vl1 = acc[mi][ni+4][2*rr+1] + bv1;
                    float r0 = gt0 / (1.0f + expf(-gt0)) * vl0;
                    float r1 = gt1 / (1.0f + expf(-gt1)) * vl1;
                    __half2 h = __floats2half2_rn(r0, r1);
                    *(__half2*)(FF + (size_t)(row + 8*rr) * (4*DM) + f) = h;
                }
            }
        }
    } else {
        #pragma unroll
        for (int mi = 0; mi < 4; mi++) {
            #pragma unroll
            for (int ni = 0; ni < 8; ni++) {
                int row = blockIdx.y * 256 + wm * 64 + mi * 16 + g;
                int col = blockIdx.x * 128 + wn * 64 + ni * 8 + 2 * tig;
                float bx = bias[col], by = bias[col + 1];
                size_t off0 = (size_t)row * N + col;
                size_t off1 = (size_t)(row + 8) * N + col;
                float r0x = acc[mi][ni][0] + bx, r0y = acc[mi][ni][1] + by;
                float r1x = acc[mi][ni][2] + bx, r1y = acc[mi][ni][3] + by;
                if (MODE == 1) {
                    __half* C = (__half*)Cv;
                    *(__half2*)(C + off0) = __floats2half2_rn(r0x, r0y);
                    *(__half2*)(C + off1) = __floats2half2_rn(r1x, r1y);
                } else {
                    float* C = (float*)Cv;
                    if (res) {
                        float2 q0 = *(const float2*)(res + off0);
                        float2 q1 = *(const float2*)(res + off1);
                        r0x += q0.x; r0y += q0.y;
                        r1x += q1.x; r1y += q1.y;
                    }
                    *(float2*)(C + off0) = make_float2(r0x, r0y);
                    *(float2*)(C + off1) = make_float2(r1x, r1y);
                }
            }
        }
    }
}

// ---------------- RoPE + head split: qkv(half) -> Q/K/V half -----------------
__global__ __launch_bounds__(256)
void rope_split_kernel(const __half* __restrict__ qkv)
{
    int idx = blockIdx.x * 256 + threadIdx.x;
    int i   = idx & 63;
    int h   = (idx >> 6) & 15;
    int row = idx >> 10;          // b*SEQ + l
    int l   = row & (SEQ - 1);
    int b   = row >> 11;
    const __half* base = qkv + (size_t)row * (3 * DM) + h * HDIM;
    float q0 = __half2float(base[i]),        q1 = __half2float(base[i + 64]);
    float k0 = __half2float(base[DM + i]),   k1 = __half2float(base[DM + i + 64]);
    float invf = powf(10000.0f, -(float)(2 * i) * (1.0f / 128.0f));
    float ang = (float)l * invf;
    float sn, cs;
    sincosf(ang, &sn, &cs);
    size_t ob = ((size_t)((b * NHEAD + h) * SEQ + l)) * HDIM;
    g_q[ob + i]      = __float2half(q0 * cs - q1 * sn);
    g_q[ob + i + 64] = __float2half(q1 * cs + q0 * sn);
    g_k[ob + i]      = __float2half(k0 * cs - k1 * sn);
    g_k[ob + i + 64] = __float2half(k1 * cs + k0 * sn);
    g_v[ob + i]      = base[2*DM + i];
    g_v[ob + i + 64] = base[2*DM + i + 64];
}

// ---------------- FP16 MMA causal flash attention ----------------------------
// 8 warps, 128 queries/CTA (16 per warp), key tiles of 64. V transposed into
// smem at load time (Vt[d][key], stride 72, key-XOR swizzle) - no ldmatrix.
// K/V smem loads amortized over 2x queries vs R13.
// Smem (half): Qs[128][136] + Ks[64][136] + Vt[128][72] + Ps[128][72] = 89,088 B.
// LPT: blockIdx.x = head, blockIdx.y = reversed q-tile (128-wide).
__global__ __launch_bounds__(256)
void attn_kernel(const __half* __restrict__ Q, const __half* __restrict__ K,
                 const __half* __restrict__ V, __half* __restrict__ O)
{
    extern __shared__ __half hsm_[];
    __half* Qs = hsm_;               // 128*136
    __half* Ks = Qs + 128 * 136;     // 64*136
    __half* Vt = Ks + 64 * 136;      // 128*72 (transposed, swizzled)
    __half* Ps = Vt + 128 * 72;      // 128*72

    int tid = threadIdx.x;
    int wid = tid >> 5, lane = tid & 31;
    int g = lane >> 2, tig = lane & 3;
    int bh = blockIdx.x;
    int q0 = (gridDim.y - 1 - blockIdx.y) * 128;   // longest CTAs first
    const __half* Qb = Q + (size_t)bh * SEQ * HDIM;
    const __half* Kb = K + (size_t)bh * SEQ * HDIM;
    const __half* Vb = V + (size_t)bh * SEQ * HDIM;

    // load Q tile: 128 rows x 128 halves
    #pragma unroll
    for (int it = 0; it < 8; it++) {
        int idx = it * 256 + tid;
        int r = idx >> 4, c8 = idx & 15;
        *(uint4*)&Qs[r * 136 + c8 * 8] =
            *(const uint4*)(Qb + (size_t)(q0 + r) * HDIM + c8 * 8);
    }

    const float scale = 0.08838834764831845f;   // 1/sqrt(128)
    float mrow[2] = {-INFINITY, -INFINITY};
    float lrow[2] = {0.f, 0.f};
    float oacc[16][4];
    #pragma unroll
    for (int d = 0; d < 16; d++) {
        oacc[d][0] = 0.f; oacc[d][1] = 0.f; oacc[d][2] = 0.f; oacc[d][3] = 0.f;
    }

    int arow0 = (wid * 16 + g) * 136;
    int arow1 = (wid * 16 + g + 8) * 136;
    int prow0 = (wid * 16 + g) * 72;
    int prow1 = (wid * 16 + g + 8) * 72;
    int qrow0 = q0 + wid * 16 + g;
    int qrow1 = qrow0 + 8;

    int nend = q0 + 64;   // key tiles cover up to q0+127
    for (int n0 = 0; n0 <= nend; n0 += 64) {
        __syncthreads();
        #pragma unroll
        for (int it = 0; it < 4; it++) {
            int idx = it * 256 + tid;
            int r = idx >> 4, c8 = idx & 15;
            *(uint4*)&Ks[r * 136 + c8 * 8] =
                *(const uint4*)(Kb + (size_t)(n0 + r) * HDIM + c8 * 8);
            uint4 vv4 = *(const uint4*)(Vb + (size_t)(n0 + r) * HDIM + c8 * 8);
            const __half* vv = (const __half*)&vv4;
            int kcol = r ^ ((c8 & 7) * 8);
            #pragma unroll
            for (int j = 0; j < 8; j++)
                Vt[(c8 * 8 + j) * 72 + kcol] = vv[j];
        }
        __syncthreads();

        // ---- S = Q K^T (16 x 64 per warp), fp16 MMA k16 ----
        float sacc[8][4];
        #pragma unroll
        for (int ni = 0; ni < 8; ni++) {
            sacc[ni][0] = 0.f; sacc[ni][1] = 0.f;
            sacc[ni][2] = 0.f; sacc[ni][3] = 0.f;
        }
        #pragma unroll
        for (int kc = 0; kc < 8; kc++) {
            int kb = kc * 16;
            uint32_t a0 = *(const uint32_t*)&Qs[arow0 + kb + 2*tig];
            uint32_t a1 = *(const uint32_t*)&Qs[arow1 + kb + 2*tig];
            uint32_t a2 = *(const uint32_t*)&Qs[arow0 + kb + 8 + 2*tig];
            uint32_t a3 = *(const uint32_t*)&Qs[arow1 + kb + 8 + 2*tig];
            #pragma unroll
            for (int ni = 0; ni < 8; ni++) {
                const __half* bp = &Ks[(ni*8 + g) * 136 + kb + 2*tig];
                uint32_t b0 = *(const uint32_t*)bp;
                uint32_t b1 = *(const uint32_t*)(bp + 8);
                MMA_F16(sacc[ni], a0, a1, a2, a3, b0, b1);
            }
        }

        // ---- online softmax (fp32) ----
        bool diag = (n0 + 63 > qrow0);
        float tm0 = -INFINITY, tm1 = -INFINITY;
        #pragma unroll
        for (int ni = 0; ni < 8; ni++) {
            int n = n0 + ni * 8 + 2 * tig;
            float s0 = sacc[ni][0] * scale;
            float s1 = sacc[ni][1] * scale;
            float s2 = sacc[ni][2] * scale;
            float s3 = sacc[ni][3] * scale;
            if (diag) {
                if (n     > qrow0) s0 = -INFINITY;
                if (n + 1 > qrow0) s1 = -INFINITY;
                if (n     > qrow1) s2 = -INFINITY;
                if (n + 1 > qrow1) s3 = -INFINITY;
            }
            sacc[ni][0] = s0; sacc[ni][1] = s1;
            sacc[ni][2] = s2; sacc[ni][3] = s3;
            tm0 = fmaxf(tm0, fmaxf(s0, s1));
            tm1 = fmaxf(tm1, fmaxf(s2, s3));
        }
        tm0 = fmaxf(tm0, __shfl_xor_sync(0xffffffffu, tm0, 1));
        tm0 = fmaxf(tm0, __shfl_xor_sync(0xffffffffu, tm0, 2));
        tm1 = fmaxf(tm1, __shfl_xor_sync(0xffffffffu, tm1, 1));
        tm1 = fmaxf(tm1, __shfl_xor_sync(0xffffffffu, tm1, 2));

        float mn0 = fmaxf(mrow[0], tm0), mn1 = fmaxf(mrow[1], tm1);
        float corr0 = expf(mrow[0] - mn0), corr1 = expf(mrow[1] - mn1);
        float ps0 = 0.f, ps1 = 0.f;
        #pragma unroll
        for (int ni = 0; ni < 8; ni++) {
            float p0 = expf(sacc[ni][0] - mn0);
            float p1 = expf(sacc[ni][1] - mn0);
            float p2 = expf(sacc[ni][2] - mn1);
            float p3 = expf(sacc[ni][3] - mn1);
            ps0 += p0 + p1; ps1 += p2 + p3;
            *(__half2*)&Ps[prow0 + ni*8 + 2*tig] = __floats2half2_rn(p0, p1);
            *(__half2*)&Ps[prow1 + ni*8 + 2*tig] = __floats2half2_rn(p2, p3);
        }
        ps0 += __shfl_xor_sync(0xffffffffu, ps0, 1);
        ps0 += __shfl_xor_sync(0xffffffffu, ps0, 2);
        ps1 += __shfl_xor_sync(0xffffffffu, ps1, 1);
        ps1 += __shfl_xor_sync(0xffffffffu, ps1, 2);
        lrow[0] = lrow[0] * corr0 + ps0;
        lrow[1] = lrow[1] * corr1 + ps1;
        mrow[0] = mn0; mrow[1] = mn1;
        #pragma unroll
        for (int d = 0; d < 16; d++) {
            oacc[d][0] *= corr0; oacc[d][1] *= corr0;
            oacc[d][2] *= corr1; oacc[d][3] *= corr1;
        }
        __syncwarp();

        // ---- O += P V  via Vt (plain LDS.32 B-frags, conflict-free) ----
        #pragma unroll
        for (int kc = 0; kc < 4; kc++) {
            int kb = kc * 16;
            uint32_t a0 = *(const uint32_t*)&Ps[prow0 + kb + 2*tig];
            uint32_t a1 = *(const uint32_t*)&Ps[prow1 + kb + 2*tig];
            uint32_t a2 = *(const uint32_t*)&Ps[prow0 + kb + 8 + 2*tig];
            uint32_t a3 = *(const uint32_t*)&Ps[prow1 + kb + 8 + 2*tig];
            #pragma unroll
            for (int dt = 0; dt < 16; dt++) {
                int swz = (dt & 7) * 8;
                const __half* vrow = &Vt[(dt * 8 + g) * 72];
                uint32_t b0 = *(const uint32_t*)&vrow[(kb + 2*tig)     ^ swz];
                uint32_t b1 = *(const uint32_t*)&vrow[(kb + 2*tig + 8) ^ swz];
                MMA_F16(oacc[dt], a0, a1, a2, a3, b0, b1);
            }
        }
        __syncwarp();
    }

    float inv0 = 1.0f / lrow[0], inv1 = 1.0f / lrow[1];
    int b = bh >> 4, h = bh & 15;
    __half* d0 = O + ((size_t)(b * SEQ + qrow0)) * DM + h * HDIM;
    __half* d1 = O + ((size_t)(b * SEQ + qrow1)) * DM + h * HDIM;
    #pragma unroll
    for (int dt = 0; dt < 16; dt++) {
        int col = dt * 8 + 2 * tig;
        *(__half2*)(d0 + col) = __floats2half2_rn(oacc[dt][0]*inv0, oacc[dt][1]*inv0);
        *(__half2*)(d1 + col) = __floats2half2_rn(oacc[dt][2]*inv1, oacc[dt][3]*inv1);
    }
}

// ---------------- launch -----------------------------------------------------
extern "C" void kernel_launch(void* const* d_in, const int* in_sizes, int n_in,
                              void* d_out, int out_size)
{
    const float* x    = (const float*)d_in[0];
    const float* Wqkv = (const float*)d_in[1];
    const float* bqkv = (const float*)d_in[2];
    const float* Wo   = (const float*)d_in[3];
    const float* bo   = (const float*)d_in[4];
    const float* g1   = (const float*)d_in[5];
    const float* g2   = (const float*)d_in[6];
    const float* Wp   = (const float*)d_in[7];
    const float* bp   = (const float*)d_in[8];
    const float* Wff  = (const float*)d_in[9];
    const float* bff  = (const float*)d_in[10];
    float* out = (float*)d_out;

    __half *pH, *pQKV, *pQ, *pK, *pV, *pO, *pFF, *pW;
    float *pX1;
    cudaGetSymbolAddress((void**)&pH,   g_h);
    cudaGetSymbolAddress((void**)&pQKV, g_qkv);
    cudaGetSymbolAddress((void**)&pQ,   g_q);
    cudaGetSymbolAddress((void**)&pK,   g_k);
    cudaGetSymbolAddress((void**)&pV,   g_v);
    cudaGetSymbolAddress((void**)&pO,   g_o);
    cudaGetSymbolAddress((void**)&pX1,  g_x1);
    cudaGetSymbolAddress((void**)&pFF,  g_ff);
    cudaGetSymbolAddress((void**)&pW,   g_w);

    __half* wqkv = pW;                       // [6144 x 2048]
    __half* wo   = pW + 12582912;            // [2048 x 2048]
    __half* wp   = pW + 16777216;            // [16384 x 2048] (permuted rows)
    __half* wff  = pW + 50331648;            // [2048 x 8192]

    static constexpr int GEMM_SMEM = 110592;
    static constexpr int ATTN_SMEM = 89088;
    cudaFuncSetAttribute(hgemm_kernel<0>, cudaFuncAttributeMaxDynamicSharedMemorySize, GEMM_SMEM);
    cudaFuncSetAttribute(hgemm_kernel<1>, cudaFuncAttributeMaxDynamicSharedMemorySize, GEMM_SMEM);
    cudaFuncSetAttribute(hgemm_kernel<2>, cudaFuncAttributeMaxDynamicSharedMemorySize, GEMM_SMEM);
    cudaFuncSetAttribute(attn_kernel, cudaFuncAttributeMaxDynamicSharedMemorySize, ATTN_SMEM);

    // 0. convert + transpose weights to half (Wp with swiglu row permutation)
    cvtw_t_kernel<false><<<dim3(6144/32,  2048/64), 256>>>(Wqkv, wqkv, 2048, 6144);
    cvtw_t_kernel<false><<<dim3(2048/32,  2048/64), 256>>>(Wo,   wo,   2048, 2048);
    cvtw_t_kernel<true ><<<dim3(16384/32, 2048/64), 256>>>(Wp,   wp,   2048, 16384);
    cvtw_t_kernel<false><<<dim3(2048/32,  8192/64), 256>>>(Wff,  wff,  8192, 2048);

    // 1. h = rms(x, g1)  (half)
    rmsnorm_kernel<<<NROWS, 256>>>(x, g1, pH);
    // 2. qkv = h @ Wqkv + bqkv  (half out)
    hgemm_kernel<1><<<dim3(6144/128, NROWS/256), 256, GEMM_SMEM>>>(
        pH, wqkv, bqkv, nullptr, pQKV, NROWS, 3*DM, DM);
    // 3. rope + split into Q/K/V (half)
    rope_split_kernel<<<(NROWS * NHEAD * 64) / 256, 256>>>(pQKV);
    // 4. causal attention -> O (half, fp16 MMA, 128-query CTAs, LPT)
    attn_kernel<<<dim3(2*NHEAD, SEQ/128), 256, ATTN_SMEM>>>(pQ, pK, pV, pO);
    // 5. x1 = O @ Wo + bo + x  (fp32 out, residual)
    hgemm_kernel<0><<<dim3(DM/128, NROWS/256), 256, GEMM_SMEM>>>(
        pO, wo, bo, x, pX1, NROWS, DM, DM);
    // 6. h2 = rms(x1, g2)  (half)
    rmsnorm_kernel<<<NROWS, 256>>>(pX1, g2, pH);
    // 7+8. ff = swiglu(h2 @ Wp + bp)  fused  (half out)
    hgemm_kernel<2><<<dim3(16384/128, NROWS/256), 256, GEMM_SMEM>>>(
        pH, wp, bp, nullptr, pFF, NROWS, 8*DM, DM);
    // 9. out = ff @ Wff_out + bff + x1  (fp32 out, residual)
    hgemm_kernel<0><<<dim3(DM/128, NROWS/256), 256, GEMM_SMEM>>>(
        pFF, wff, bff, pX1, out, NROWS, DM, 4*DM);
}

// round 16
// speedup vs baseline: 1.5530x; 1.0064x over previous
#include <cuda_runtime.h>
#include <cuda_fp16.h>
#include <math.h>
#include <stdint.h>

static constexpr int SEQ   = 2048;
static constexpr int DM    = 2048;
static constexpr int NHEAD = 16;
static constexpr int HDIM  = 128;
static constexpr int NROWS = 4096;   // B * L

// ---------------- scratch (device globals; no allocation allowed) ----------
__device__ __align__(16) __half g_h  [(size_t)NROWS * DM];          // rms out (half)
__device__ __align__(16) __half g_qkv[(size_t)NROWS * 3 * DM];      // qkv (half)
__device__ __align__(16) __half g_q  [(size_t)NROWS * DM];          // rope'd half
__device__ __align__(16) __half g_k  [(size_t)NROWS * DM];
__device__ __align__(16) __half g_v  [(size_t)NROWS * DM];
__device__ __align__(16) __half g_o  [(size_t)NROWS * DM];          // attn out (half)
__device__ __align__(16) float  g_x1 [(size_t)NROWS * DM];          // residual fp32
__device__ __align__(16) __half g_ff [(size_t)NROWS * 4 * DM];      // swiglu out (half)
// half TRANSPOSED weights: Wqkv^T | Wo^T | Wp^T(permuted) | Wff^T
__device__ __align__(16) __half g_w  [(size_t)67108864];

__device__ __forceinline__ void cp_async16(uint32_t smem, const void* g) {
    asm volatile("cp.async.cg.shared.global [%0], [%1], 16;" :: "r"(smem), "l"(g));
}
__device__ __forceinline__ void cp_commit() {
    asm volatile("cp.async.commit_group;");
}
template<int N> __device__ __forceinline__ void cp_wait() {
    asm volatile("cp.async.wait_group %0;" :: "n"(N));
}

#define MMA_F16(acc, a0, a1, a2, a3, b0, b1)                                   \
    asm volatile(                                                              \
        "mma.sync.aligned.m16n8k16.row.col.f32.f16.f16.f32 "                   \
        "{%0,%1,%2,%3}, {%4,%5,%6,%7}, {%8,%9}, {%0,%1,%2,%3};"                \
        : "+f"(acc[0]), "+f"(acc[1]), "+f"(acc[2]), "+f"(acc[3])               \
        : "r"(a0), "r"(a1), "r"(a2), "r"(a3), "r"(b0), "r"(b1))

// ---------------- weight half convert + transpose: Wt[n][k] = W[k][n] --------
// 64(n) x 64(k) tiles, float4 global loads, 128B-coalesced half2 stores.
// PERM: swiglu row permutation for Wp (gate/value interleaved per 64-row block)
template<bool PERM>
__global__ __launch_bounds__(256)
void cvtw_t_kernel(const float* __restrict__ W, __half* __restrict__ Wt,
                   int K, int N)
{
    __shared__ float tile[64][65];    // [n][k]
    int tid = threadIdx.x;
    int n0 = blockIdx.x * 64, k0 = blockIdx.y * 64;
    // load 64(k) x 64(n) elements as float4 along n: 1024 float4, 4 per thread
    #pragma unroll
    for (int it = 0; it < 4; it++) {
        int idx = it * 256 + tid;
        int r = idx >> 4;          // k row 0..63
        int c = idx & 15;          // float4 index in n
        float4 v = *(const float4*)(W + (size_t)(k0 + r) * N + n0 + c * 4);
        tile[c*4+0][r] = v.x;
        tile[c*4+1][r] = v.y;
        tile[c*4+2][r] = v.z;
        tile[c*4+3][r] = v.w;
    }
    __syncthreads();
    // store: 8 warps x 8 n-rows each; lane writes half2 at k = 2*lane (128B/row)
    int wid = tid >> 5, lane = tid & 31;
    #pragma unroll
    for (int j = 0; j < 8; j++) {
        int nrow = wid * 8 + j;
        int n = n0 + nrow;
        int r = n;
        if (PERM) {
            int half_n = N >> 1;                 // 8192
            if (n < half_n) r = (n >> 5) * 64 + (n & 31);
            else { int f = n - half_n; r = (f >> 5) * 64 + 32 + (f & 31); }
        }
        float v0 = tile[nrow][2 * lane];
        float v1 = tile[nrow][2 * lane + 1];
        *(__half2*)(Wt + (size_t)r * K + k0 + 2 * lane) = __floats2half2_rn(v0, v1);
    }
}

// ---------------- RMSNorm (half output) --------------------------------------
__global__ __launch_bounds__(256)
void rmsnorm_kernel(const float* __restrict__ x, const float* __restrict__ g,
                    __half* __restrict__ out)
{
    int row = blockIdx.x;
    int tid = threadIdx.x;
    const float4* xr = (const float4*)(x + (size_t)row * DM);
    const float4* gr = (const float4*)g;
    float4 v0 = xr[2*tid], v1 = xr[2*tid + 1];
    float ss = v0.x*v0.x + v0.y*v0.y + v0.z*v0.z + v0.w*v0.w
             + v1.x*v1.x + v1.y*v1.y + v1.z*v1.z + v1.w*v1.w;
    #pragma unroll
    for (int off = 16; off > 0; off >>= 1)
        ss += __shfl_xor_sync(0xffffffffu, ss, off);
    __shared__ float wsum[8];
    if ((tid & 31) == 0) wsum[tid >> 5] = ss;
    __syncthreads();
    float tot = wsum[0]+wsum[1]+wsum[2]+wsum[3]+wsum[4]+wsum[5]+wsum[6]+wsum[7];
    float sc = rsqrtf(tot * (1.0f / (float)DM) + 1e-8f);
    float4 ga = gr[2*tid], gb = gr[2*tid + 1];
    __half2 h0 = __floats2half2_rn(v0.x*sc*ga.x, v0.y*sc*ga.y);
    __half2 h1 = __floats2half2_rn(v0.z*sc*ga.z, v0.w*sc*ga.w);
    __half2 h2 = __floats2half2_rn(v1.x*sc*gb.x, v1.y*sc*gb.y);
    __half2 h3 = __floats2half2_rn(v1.z*sc*gb.z, v1.w*sc*gb.w);
    uint4 pk;
    pk.x = *(uint32_t*)&h0; pk.y = *(uint32_t*)&h1;
    pk.z = *(uint32_t*)&h2; pk.w = *(uint32_t*)&h3;
    ((uint4*)(out + (size_t)row * DM))[tid] = pk;
}

// ---------------- FP16 tensor-core GEMM, cp.async double-buffered ------------
// R13-proven 2-stage version.
// MODE 0: float out + optional residual; MODE 1: half out; MODE 2: swiglu->half
// 256x128 CTA tile, BK=64, 2-stage, 8 warps (4x2), warp tile 64x64.
template<int MODE>
__global__ __launch_bounds__(256, 1)
void hgemm_kernel(const __half* __restrict__ A, const __half* __restrict__ Bt,
                  const float* __restrict__ bias, const float* __restrict__ res,
                  void* __restrict__ Cv, int M, int N, int K)
{
    extern __shared__ __half hsm[];
    __half* As = hsm;                  // 2 stages x 256 x 72
    __half* Bs = hsm + 36864;          // 2 stages x 128 x 72

    int tid = threadIdx.x;
    int wid = tid >> 5, lane = tid & 31;
    int wm  = wid >> 1;        // 0..3 -> 64 rows
    int wn  = wid & 1;         // 0..1 -> 64 cols
    int g   = lane >> 2;       // 0..7
    int tig = lane & 3;        // 0..3

    const __half* Ab = A  + (size_t)blockIdx.y * 256 * K;
    const __half* Bb = Bt + (size_t)blockIdx.x * 128 * K;

    uint32_t as_base = (uint32_t)__cvta_generic_to_shared(As);
    uint32_t bs_base = (uint32_t)__cvta_generic_to_shared(Bs);

    int arow[8], acol8[8], brow[4], bcol8[4];
    #pragma unroll
    for (int i = 0; i < 8; i++) {
        int c = tid + 256 * i;
        arow[i] = c >> 3; acol8[i] = (c & 7) * 8;
    }
    #pragma unroll
    for (int i = 0; i < 4; i++) {
        int c = tid + 256 * i;
        brow[i] = c >> 3; bcol8[i] = (c & 7) * 8;
    }

    float acc[4][8][4];
    #pragma unroll
    for (int i = 0; i < 4; i++)
        #pragma unroll
        for (int j = 0; j < 8; j++) {
            acc[i][j][0] = 0.f; acc[i][j][1] = 0.f;
            acc[i][j][2] = 0.f; acc[i][j][3] = 0.f;
        }

    const int NT = K >> 6;

    #pragma unroll
    for (int i = 0; i < 8; i++)
        cp_async16(as_base + (uint32_t)((arow[i] * 72 + acol8[i]) * 2),
                   Ab + (size_t)arow[i] * K + acol8[i]);
    #pragma unroll
    for (int i = 0; i < 4; i++)
        cp_async16(bs_base + (uint32_t)((brow[i] * 72 + bcol8[i]) * 2),
                   Bb + (size_t)brow[i] * K + bcol8[i]);
    cp_commit();

    for (int t = 0; t < NT; t++) {
        int buf = t & 1;
        if (t + 1 < NT) {
            int nb = (t + 1) & 1;
            int k0 = (t + 1) * 64;
            uint32_t aoff = as_base + (uint32_t)(nb * 18432 * 2);
            uint32_t boff = bs_base + (uint32_t)(nb * 9216 * 2);
            #pragma unroll
            for (int i = 0; i < 8; i++)
                cp_async16(aoff + (uint32_t)((arow[i] * 72 + acol8[i]) * 2),
                           Ab + (size_t)arow[i] * K + k0 + acol8[i]);
            #pragma unroll
            for (int i = 0; i < 4; i++)
                cp_async16(boff + (uint32_t)((brow[i] * 72 + bcol8[i]) * 2),
                           Bb + (size_t)brow[i] * K + k0 + bcol8[i]);
            cp_commit();
            cp_wait<1>();
        } else {
            cp_wait<0>();
        }
        __syncthreads();

        int abuf = buf * 18432, bbuf = buf * 9216;
        #pragma unroll
        for (int ks = 0; ks < 4; ks++) {
            int kb = ks * 16;
            uint32_t af[4][4], bf[8][2];
            #pragma unroll
            for (int mi = 0; mi < 4; mi++) {
                int row = wm * 64 + mi * 16 + g;
                const __half* r0 = &As[abuf + row * 72 + kb + 2 * tig];
                const __half* r1 = &As[abuf + (row + 8) * 72 + kb + 2 * tig];
                af[mi][0] = *(const uint32_t*)r0;
                af[mi][1] = *(const uint32_t*)r1;
                af[mi][2] = *(const uint32_t*)(r0 + 8);
                af[mi][3] = *(const uint32_t*)(r1 + 8);
            }
            #pragma unroll
            for (int ni = 0; ni < 8; ni++) {
                int col = wn * 64 + ni * 8 + g;
                const __half* b0 = &Bs[bbuf + col * 72 + kb + 2 * tig];
                bf[ni][0] = *(const uint32_t*)b0;
                bf[ni][1] = *(const uint32_t*)(b0 + 8);
            }
            #pragma unroll
            for (int mi = 0; mi < 4; mi++)
                #pragma unroll
                for (int ni = 0; ni < 8; ni++)
                    MMA_F16(acc[mi][ni], af[mi][0], af[mi][1], af[mi][2], af[mi][3],
                            bf[ni][0], bf[ni][1]);
        }
        __syncthreads();
    }

    if (MODE == 2) {
        // swiglu fused: warp block holds [gate f..f+31 | value f..f+31]
        __half* FF = (__half*)Cv;
        int b = blockIdx.x * 2 + wn;
        #pragma unroll
        for (int mi = 0; mi < 4; mi++) {
            int row = blockIdx.y * 256 + wm * 64 + mi * 16 + g;
            #pragma unroll
            for (int ni = 0; ni < 4; ni++) {
                int off = ni * 8 + 2 * tig;
                int f   = b * 32 + off;              // ff column
                float bg0 = bias[f],        bg1 = bias[f + 1];
                float bv0 = bias[8192 + f], bv1 = bias[8192 + f + 1];
                #pragma unroll
                for (int rr = 0; rr < 2; rr++) {
                    float gt0 = acc[mi][ni][2*rr]   + bg0;
                    float gt1 = acc[mi][ni][2*rr+1] + bg1;
                    float vl0 = acc[mi][ni+4][2*rr]   + bv0;
                    float vl1 = acc[mi][ni+4][2*rr+1] + bv1;
                    float r0 = gt0 / (1.0f + expf(-gt0)) * vl0;
                    float r1 = gt1 / (1.0f + expf(-gt1)) * vl1;
                    __half2 h = __floats2half2_rn(r0, r1);
                    *(__half2*)(FF + (size_t)(row + 8*rr) * (4*DM) + f) = h;
                }
            }
        }
    } else {
        #pragma unroll
        for (int mi = 0; mi < 4; mi++) {
            #pragma unroll
            for (int ni = 0; ni < 8; ni++) {
                int row = blockIdx.y * 256 + wm * 64 + mi * 16 + g;
                int col = blockIdx.x * 128 + wn * 64 + ni * 8 + 2 * tig;
                float bx = bias[col], by = bias[col + 1];
                size_t off0 = (size_t)row * N + col;
                size_t off1 = (size_t)(row + 8) * N + col;
                float r0x = acc[mi][ni][0] + bx, r0y = acc[mi][ni][1] + by;
                float r1x = acc[mi][ni][2] + bx, r1y = acc[mi][ni][3] + by;
                if (MODE == 1) {
                    __half* C = (__half*)Cv;
                    *(__half2*)(C + off0) = __floats2half2_rn(r0x, r0y);
                    *(__half2*)(C + off1) = __floats2half2_rn(r1x, r1y);
                } else {
                    float* C = (float*)Cv;
                    if (res) {
                        float2 q0 = *(const float2*)(res + off0);
                        float2 q1 = *(const float2*)(res + off1);
                        r0x += q0.x; r0y += q0.y;
                        r1x += q1.x; r1y += q1.y;
                    }
                    *(float2*)(C + off0) = make_float2(r0x, r0y);
                    *(float2*)(C + off1) = make_float2(r1x, r1y);
                }
            }
        }
    }
}

// ---------------- RoPE + head split: qkv(half) -> Q/K/V half -----------------
__global__ __launch_bounds__(256)
void rope_split_kernel(const __half* __restrict__ qkv)
{
    int idx = blockIdx.x * 256 + threadIdx.x;
    int i   = idx & 63;
    int h   = (idx >> 6) & 15;
    int row = idx >> 10;          // b*SEQ + l
    int l   = row & (SEQ - 1);
    int b   = row >> 11;
    const __half* base = qkv + (size_t)row * (3 * DM) + h * HDIM;
    float q0 = __half2float(base[i]),        q1 = __half2float(base[i + 64]);
    float k0 = __half2float(base[DM + i]),   k1 = __half2float(base[DM + i + 64]);
    float invf = powf(10000.0f, -(float)(2 * i) * (1.0f / 128.0f));
    float ang = (float)l * invf;
    float sn, cs;
    sincosf(ang, &sn, &cs);
    size_t ob = ((size_t)((b * NHEAD + h) * SEQ + l)) * HDIM;
    g_q[ob + i]      = __float2half(q0 * cs - q1 * sn);
    g_q[ob + i + 64] = __float2half(q1 * cs + q0 * sn);
    g_k[ob + i]      = __float2half(k0 * cs - k1 * sn);
    g_k[ob + i + 64] = __float2half(k1 * cs + k0 * sn);
    g_v[ob + i]      = base[2*DM + i];
    g_v[ob + i + 64] = base[2*DM + i + 64];
}

// ---------------- FP16 MMA causal flash attention (R13-proven) ---------------
// 4 warps, 64 queries/CTA, key tiles of 64. V transposed into smem at load time
// (Vt[d][key], stride 72, key-XOR swizzle) so PV B-frags are plain LDS.32.
// Smem (half): Qs[64][136] + Ks[64][136] + Vt[128][72] + Ps[64][72] = 62,464 B.
// LPT: blockIdx.x = head, blockIdx.y = reversed q-tile.
__global__ __launch_bounds__(128)
void attn_kernel(const __half* __restrict__ Q, const __half* __restrict__ K,
                 const __half* __restrict__ V, __half* __restrict__ O)
{
    extern __shared__ __half hsm_[];
    __half* Qs = hsm_;               // 64*136
    __half* Ks = Qs + 64 * 136;
    __half* Vt = Ks + 64 * 136;      // 128*72 (transposed, swizzled)
    __half* Ps = Vt + 128 * 72;      // 64*72

    int tid = threadIdx.x;
    int wid = tid >> 5, lane = tid & 31;
    int g = lane >> 2, tig = lane & 3;
    int bh = blockIdx.x;
    int q0 = (gridDim.y - 1 - blockIdx.y) * 64;    // longest CTAs first
    const __half* Qb = Q + (size_t)bh * SEQ * HDIM;
    const __half* Kb = K + (size_t)bh * SEQ * HDIM;
    const __half* Vb = V + (size_t)bh * SEQ * HDIM;

    #pragma unroll
    for (int it = 0; it < 8; it++) {
        int idx = it * 128 + tid;
        int r = idx >> 4, c8 = idx & 15;
        *(uint4*)&Qs[r * 136 + c8 * 8] =
            *(const uint4*)(Qb + (size_t)(q0 + r) * HDIM + c8 * 8);
    }

    const float scale = 0.08838834764831845f;   // 1/sqrt(128)
    float mrow[2] = {-INFINITY, -INFINITY};
    float lrow[2] = {0.f, 0.f};
    float oacc[16][4];
    #pragma unroll
    for (int d = 0; d < 16; d++) {
        oacc[d][0] = 0.f; oacc[d][1] = 0.f; oacc[d][2] = 0.f; oacc[d][3] = 0.f;
    }

    int arow0 = (wid * 16 + g) * 136;
    int arow1 = (wid * 16 + g + 8) * 136;
    int prow0 = (wid * 16 + g) * 72;
    int prow1 = (wid * 16 + g + 8) * 72;
    int qrow0 = q0 + wid * 16 + g;
    int qrow1 = qrow0 + 8;

    for (int n0 = 0; n0 <= q0; n0 += 64) {
        __syncthreads();
        #pragma unroll
        for (int it = 0; it < 8; it++) {
            int idx = it * 128 + tid;
            int r = idx >> 4, c8 = idx & 15;
            *(uint4*)&Ks[r * 136 + c8 * 8] =
                *(const uint4*)(Kb + (size_t)(n0 + r) * HDIM + c8 * 8);
            uint4 vv4 = *(const uint4*)(Vb + (size_t)(n0 + r) * HDIM + c8 * 8);
            const __half* vv = (const __half*)&vv4;
            int kcol = r ^ ((c8 & 7) * 8);
            #pragma unroll
            for (int j = 0; j < 8; j++)
                Vt[(c8 * 8 + j) * 72 + kcol] = vv[j];
        }
        __syncthreads();

        float sacc[8][4];
        #pragma unroll
        for (int ni = 0; ni < 8; ni++) {
            sacc[ni][0] = 0.f; sacc[ni][1] = 0.f;
            sacc[ni][2] = 0.f; sacc[ni][3] = 0.f;
        }
        #pragma unroll
        for (int kc = 0; kc < 8; kc++) {
            int kb = kc * 16;
            uint32_t a0 = *(const uint32_t*)&Qs[arow0 + kb + 2*tig];
            uint32_t a1 = *(const uint32_t*)&Qs[arow1 + kb + 2*tig];
            uint32_t a2 = *(const uint32_t*)&Qs[arow0 + kb + 8 + 2*tig];
            uint32_t a3 = *(const uint32_t*)&Qs[arow1 + kb + 8 + 2*tig];
            #pragma unroll
            for (int ni = 0; ni < 8; ni++) {
                const __half* bp = &Ks[(ni*8 + g) * 136 + kb + 2*tig];
                uint32_t b0 = *(const uint32_t*)bp;
                uint32_t b1 = *(const uint32_t*)(bp + 8);
                MMA_F16(sacc[ni], a0, a1, a2, a3, b0, b1);
            }
        }

        bool diag = (n0 == q0);
        float tm0 = -INFINITY, tm1 = -INFINITY;
        #pragma unroll
        for (int ni = 0; ni < 8; ni++) {
            int n = n0 + ni * 8 + 2 * tig;
            float s0 = sacc[ni][0] * scale;
            float s1 = sacc[ni][1] * scale;
            float s2 = sacc[ni][2] * scale;
            float s3 = sacc[ni][3] * scale;
            if (diag) {
                if (n     > qrow0) s0 = -INFINITY;
                if (n + 1 > qrow0) s1 = -INFINITY;
                if (n     > qrow1) s2 = -INFINITY;
                if (n + 1 > qrow1) s3 = -INFINITY;
            }
            sacc[ni][0] = s0; sacc[ni][1] = s1;
            sacc[ni][2] = s2; sacc[ni][3] = s3;
            tm0 = fmaxf(tm0, fmaxf(s0, s1));
            tm1 = fmaxf(tm1, fmaxf(s2, s3));
        }
        tm0 = fmaxf(tm0, __shfl_xor_sync(0xffffffffu, tm0, 1));
        tm0 = fmaxf(tm0, __shfl_xor_sync(0xffffffffu, tm0, 2));
        tm1 = fmaxf(tm1, __shfl_xor_sync(0xffffffffu, tm1, 1));
        tm1 = fmaxf(tm1, __shfl_xor_sync(0xffffffffu, tm1, 2));

        float mn0 = fmaxf(mrow[0], tm0), mn1 = fmaxf(mrow[1], tm1);
        float corr0 = expf(mrow[0] - mn0), corr1 = expf(mrow[1] - mn1);
        float ps0 = 0.f, ps1 = 0.f;
        #pragma unroll
        for (int ni = 0; ni < 8; ni++) {
            float p0 = expf(sacc[ni][0] - mn0);
            float p1 = expf(sacc[ni][1] - mn0);
            float p2 = expf(sacc[ni][2] - mn1);
            float p3 = expf(sacc[ni][3] - mn1);
            ps0 += p0 + p1; ps1 += p2 + p3;
            *(__half2*)&Ps[prow0 + ni*8 + 2*tig] = __floats2half2_rn(p0, p1);
            *(__half2*)&Ps[prow1 + ni*8 + 2*tig] = __floats2half2_rn(p2, p3);
        }
        ps0 += __shfl_xor_sync(0xffffffffu, ps0, 1);
        ps0 += __shfl_xor_sync(0xffffffffu, ps0, 2);
        ps1 += __shfl_xor_sync(0xffffffffu, ps1, 1);
        ps1 += __shfl_xor_sync(0xffffffffu, ps1, 2);
        lrow[0] = lrow[0] * corr0 + ps0;
        lrow[1] = lrow[1] * corr1 + ps1;
        mrow[0] = mn0; mrow[1] = mn1;
        #pragma unroll
        for (int d = 0; d < 16; d++) {
            oacc[d][0] *= corr0; oacc[d][1] *= corr0;
            oacc[d][2] *= corr1; oacc[d][3] *= corr1;
        }
        __syncwarp();

        #pragma unroll
        for (int kc = 0; kc < 4; kc++) {
            int kb = kc * 16;
            uint32_t a0 = *(const uint32_t*)&Ps[prow0 + kb + 2*tig];
            uint32_t a1 = *(const uint32_t*)&Ps[prow1 + kb + 2*tig];
            uint32_t a2 = *(const uint32_t*)&Ps[prow0 + kb + 8 + 2*tig];
            uint32_t a3 = *(const uint32_t*)&Ps[prow1 + kb + 8 + 2*tig];
            #pragma unroll
            for (int dt = 0; dt < 16; dt++) {
                int swz = (dt & 7) * 8;
                const __half* vrow = &Vt[(dt * 8 + g) * 72];
                uint32_t b0 = *(const uint32_t*)&vrow[(kb + 2*tig)     ^ swz];
                uint32_t b1 = *(const uint32_t*)&vrow[(kb + 2*tig + 8) ^ swz];
                MMA_F16(oacc[dt], a0, a1, a2, a3, b0, b1);
            }
        }
        __syncwarp();
    }

    float inv0 = 1.0f / lrow[0], inv1 = 1.0f / lrow[1];
    int b = bh >> 4, h = bh & 15;
    __half* d0 = O + ((size_t)(b * SEQ + qrow0)) * DM + h * HDIM;
    __half* d1 = O + ((size_t)(b * SEQ + qrow1)) * DM + h * HDIM;
    #pragma unroll
    for (int dt = 0; dt < 16; dt++) {
        int col = dt * 8 + 2 * tig;
        *(__half2*)(d0 + col) = __floats2half2_rn(oacc[dt][0]*inv0, oacc[dt][1]*inv0);
        *(__half2*)(d1 + col) = __floats2half2_rn(oacc[dt][2]*inv1, oacc[dt][3]*inv1);
    }
}

// ---------------- launch -----------------------------------------------------
extern "C" void kernel_launch(void* const* d_in, const int* in_sizes, int n_in,
                              void* d_out, int out_size)
{
    const float* x    = (const float*)d_in[0];
    const float* Wqkv = (const float*)d_in[1];
    const float* bqkv = (const float*)d_in[2];
    const float* Wo   = (const float*)d_in[3];
    const float* bo   = (const float*)d_in[4];
    const float* g1   = (const float*)d_in[5];
    const float* g2   = (const float*)d_in[6];
    const float* Wp   = (const float*)d_in[7];
    const float* bp   = (const float*)d_in[8];
    const float* Wff  = (const float*)d_in[9];
    const float* bff  = (const float*)d_in[10];
    float* out = (float*)d_out;

    __half *pH, *pQKV, *pQ, *pK, *pV, *pO, *pFF, *pW;
    float *pX1;
    cudaGetSymbolAddress((void**)&pH,   g_h);
    cudaGetSymbolAddress((void**)&pQKV, g_qkv);
    cudaGetSymbolAddress((void**)&pQ,   g_q);
    cudaGetSymbolAddress((void**)&pK,   g_k);
    cudaGetSymbolAddress((void**)&pV,   g_v);
    cudaGetSymbolAddress((void**)&pO,   g_o);
    cudaGetSymbolAddress((void**)&pX1,  g_x1);
    cudaGetSymbolAddress((void**)&pFF,  g_ff);
    cudaGetSymbolAddress((void**)&pW,   g_w);

    __half* wqkv = pW;                       // [6144 x 2048]
    __half* wo   = pW + 12582912;            // [2048 x 2048]
    __half* wp   = pW + 16777216;            // [16384 x 2048] (permuted rows)
    __half* wff  = pW + 50331648;            // [2048 x 8192]

    static constexpr int GEMM_SMEM = 110592;
    static constexpr int ATTN_SMEM = 62464;
    cudaFuncSetAttribute(hgemm_kernel<0>, cudaFuncAttributeMaxDynamicSharedMemorySize, GEMM_SMEM);
    cudaFuncSetAttribute(hgemm_kernel<1>, cudaFuncAttributeMaxDynamicSharedMemorySize, GEMM_SMEM);
    cudaFuncSetAttribute(hgemm_kernel<2>, cudaFuncAttributeMaxDynamicSharedMemorySize, GEMM_SMEM);
    cudaFuncSetAttribute(attn_kernel, cudaFuncAttributeMaxDynamicSharedMemorySize, ATTN_SMEM);

    // 0. convert + transpose weights to half (Wp with swiglu row permutation)
    cvtw_t_kernel<false><<<dim3(6144/64,  2048/64), 256>>>(Wqkv, wqkv, 2048, 6144);
    cvtw_t_kernel<false><<<dim3(2048/64,  2048/64), 256>>>(Wo,   wo,   2048, 2048);
    cvtw_t_kernel<true ><<<dim3(16384/64, 2048/64), 256>>>(Wp,   wp,   2048, 16384);
    cvtw_t_kernel<false><<<dim3(2048/64,  8192/64), 256>>>(Wff,  wff,  8192, 2048);

    // 1. h = rms(x, g1)  (half)
    rmsnorm_kernel<<<NROWS, 256>>>(x, g1, pH);
    // 2. qkv = h @ Wqkv + bqkv  (half out)
    hgemm_kernel<1><<<dim3(6144/128, NROWS/256), 256, GEMM_SMEM>>>(
        pH, wqkv, bqkv, nullptr, pQKV, NROWS, 3*DM, DM);
    // 3. rope + split into Q/K/V (half)
    rope_split_kernel<<<(NROWS * NHEAD * 64) / 256, 256>>>(pQKV);
    // 4. causal attention -> O (half, fp16 MMA, 64-query CTAs, LPT)
    attn_kernel<<<dim3(2*NHEAD, SEQ/64), 128, ATTN_SMEM>>>(pQ, pK, pV, pO);
    // 5. x1 = O @ Wo + bo + x  (fp32 out, residual)
    hgemm_kernel<0><<<dim3(DM/128, NROWS/256), 256, GEMM_SMEM>>>(
        pO, wo, bo, x, pX1, NROWS, DM, DM);
    // 6. h2 = rms(x1, g2)  (half)
    rmsnorm_kernel<<<NROWS, 256>>>(pX1, g2, pH);
    // 7+8. ff = swiglu(h2 @ Wp + bp)  fused  (half out)
    hgemm_kernel<2><<<dim3(16384/128, NROWS/256), 256, GEMM_SMEM>>>(
        pH, wp, bp, nullptr, pFF, NROWS, 8*DM, DM);
    // 9. out = ff @ Wff_out + bff + x1  (fp32 out, residual)
    hgemm_kernel<0><<<dim3(DM/128, NROWS/256), 256, GEMM_SMEM>>>(
        pFF, wff, bff, pX1, out, NROWS, DM, 4*DM);
}